// round 1
// baseline (speedup 1.0000x reference)
#include <cuda_runtime.h>
#include <math.h>

#define D 16
#define EF 8
#define NLAYERS 3
#define MAX_N 50048
#define MAX_E 500224
#define MAX_G 512
#define FP_SCALE 4294967296.0f
#define FP_INV 2.3283064365386963e-10

// ---------------- static device scratch (no runtime allocation) ----------------
__device__ float     g_he   [MAX_E * D];   // edge MLP output, original edge order
__device__ float     g_he_s [MAX_E * D];   // src-sorted
__device__ float     g_msg  [MAX_E * D];   // messages in dst-slot order
__device__ int       g_ds   [MAX_E];       // src-slot -> dst-slot
__device__ int       g_deg_src[MAX_N], g_deg_dst[MAX_N];
__device__ int       g_off_src[MAX_N + 1], g_off_dst[MAX_N + 1];
__device__ int       g_cur_src[MAX_N], g_cur_dst[MAX_N];
__device__ int       g_goff[MAX_G + 1];
__device__ float     g_gmat [MAX_N * 256]; // per-node transform g[n][o*16+j]
__device__ float     g_bt   [MAX_N * D];   // per-node bias term
__device__ float     g_hbuf [MAX_N * D];   // node features between layers
__device__ float     g_hpre [MAX_N * D];   // pre-BN activations
__device__ long long g_bnsum[32];          // [0:16] sum, [16:32] sumsq (fixed point)

// ---------------- K_zero: reset counters ----------------
__global__ void K_zero(int N) {
    int i = blockIdx.x * blockDim.x + threadIdx.x;
    if (i < N) {
        g_deg_src[i] = 0; g_deg_dst[i] = 0;
        g_cur_src[i] = 0; g_cur_dst[i] = 0;
    }
}

// ---------------- K_edge: he = tanh(edge_attr @ w1 + b1), degree counts --------
__global__ void K_edge(const float* __restrict__ edge_attr,
                       const float* __restrict__ w1,
                       const float* __restrict__ b1,
                       const int*   __restrict__ edge_index,
                       int E) {
    __shared__ float s_w1[EF * D];
    __shared__ float s_b1[D];
    int tid = threadIdx.x;
    if (tid < EF * D) s_w1[tid] = w1[tid];
    if (tid < D)      s_b1[tid] = b1[tid];
    __syncthreads();

    int e = blockIdx.x * blockDim.x + tid;
    if (e >= E) return;

    const float4* ea = (const float4*)(edge_attr + (size_t)e * EF);
    float4 a0 = ea[0], a1 = ea[1];
    float a[8] = {a0.x, a0.y, a0.z, a0.w, a1.x, a1.y, a1.z, a1.w};

    float out[D];
#pragma unroll
    for (int j = 0; j < D; j++) {
        float acc = s_b1[j];
#pragma unroll
        for (int k = 0; k < EF; k++) acc += a[k] * s_w1[k * D + j];
        out[j] = tanhf(acc);
    }
    float4* dst4 = (float4*)(g_he + (size_t)e * D);
    dst4[0] = make_float4(out[0], out[1], out[2], out[3]);
    dst4[1] = make_float4(out[4], out[5], out[6], out[7]);
    dst4[2] = make_float4(out[8], out[9], out[10], out[11]);
    dst4[3] = make_float4(out[12], out[13], out[14], out[15]);

    int s = edge_index[e];
    int d = edge_index[E + e];
    atomicAdd(&g_deg_src[s], 1);
    atomicAdd(&g_deg_dst[d], 1);
}

// ---------------- K_scan: exclusive scan (single block, 1024 threads) ----------
// mode 0: deg_src -> off_src ; mode 1: deg_dst -> off_dst ; mode 2: ext_in -> goff
__global__ void K_scan(int mode, const int* __restrict__ ext_in, int n) {
    __shared__ int s_warp[33];
    const int* in;
    int* out;
    if (mode == 0)      { in = g_deg_src; out = g_off_src; }
    else if (mode == 1) { in = g_deg_dst; out = g_off_dst; }
    else                { in = ext_in;    out = g_goff;    }

    int tid = threadIdx.x, lane = tid & 31, wid = tid >> 5;
    int carry = 0;
    for (int base = 0; base < n; base += 4096) {
        int i0 = base + tid * 4;
        int v0 = (i0 + 0 < n) ? in[i0 + 0] : 0;
        int v1 = (i0 + 1 < n) ? in[i0 + 1] : 0;
        int v2 = (i0 + 2 < n) ? in[i0 + 2] : 0;
        int v3 = (i0 + 3 < n) ? in[i0 + 3] : 0;
        int t = v0 + v1 + v2 + v3;
        int x = t;
#pragma unroll
        for (int dl = 1; dl < 32; dl <<= 1) {
            int y = __shfl_up_sync(0xffffffffu, x, dl);
            if (lane >= dl) x += y;
        }
        if (lane == 31) s_warp[wid] = x;
        __syncthreads();
        if (wid == 0) {
            int w = s_warp[lane];
            int xw = w;
#pragma unroll
            for (int dl = 1; dl < 32; dl <<= 1) {
                int y = __shfl_up_sync(0xffffffffu, xw, dl);
                if (lane >= dl) xw += y;
            }
            s_warp[lane] = xw - w;
            if (lane == 31) s_warp[32] = xw;
        }
        __syncthreads();
        int excl = carry + s_warp[wid] + (x - t);
        if (i0 + 0 < n) out[i0 + 0] = excl;
        if (i0 + 1 < n) out[i0 + 1] = excl + v0;
        if (i0 + 2 < n) out[i0 + 2] = excl + v0 + v1;
        if (i0 + 3 < n) out[i0 + 3] = excl + v0 + v1 + v2;
        carry += s_warp[32];
        __syncthreads();
    }
    if (tid == 0) out[n] = carry;
}

// ---------------- K_fill: scatter edges into src-CSR slots, record dst slot ----
__global__ void K_fill(const int* __restrict__ edge_index, int E) {
    int e = blockIdx.x * blockDim.x + threadIdx.x;
    if (e >= E) return;
    int s = edge_index[e];
    int d = edge_index[E + e];
    int ps = g_off_src[s] + atomicAdd(&g_cur_src[s], 1);
    int pd = g_off_dst[d] + atomicAdd(&g_cur_dst[d], 1);
    g_ds[ps] = pd;
    const float4* src4 = (const float4*)(g_he + (size_t)e * D);
    float4* dst4 = (float4*)(g_he_s + (size_t)ps * D);
    dst4[0] = src4[0]; dst4[1] = src4[1]; dst4[2] = src4[2]; dst4[3] = src4[3];
}

// ---------------- K_g: per-node transform g[n][o*16+j], bt[n][o] ---------------
// g[n][o,j] = sum_i h[n][i] * w2[j*256 + i*16 + o];  bt[n][o] = sum_i h[n][i]*b2[i*16+o]
__global__ void K_g(const float* __restrict__ h_in,
                    const float* __restrict__ w2,
                    const float* __restrict__ b2,
                    int N) {
    __shared__ float s_w2[D * 256];
    __shared__ float s_b2[256];
    int tid = threadIdx.x;
    for (int i = tid; i < D * 256; i += blockDim.x) s_w2[i] = w2[i];
    for (int i = tid; i < 256; i += blockDim.x)     s_b2[i] = b2[i];
    if (blockIdx.x == 0 && tid < 32) g_bnsum[tid] = 0;  // reset BN accumulators
    __syncthreads();

    int gi = blockIdx.x * blockDim.x + tid;
    if (gi >= N * D) return;
    int n = gi >> 4, o = gi & 15;

    float acc[D];
#pragma unroll
    for (int j = 0; j < D; j++) acc[j] = 0.f;
    float bt = 0.f;
#pragma unroll
    for (int i = 0; i < D; i++) {
        float hv = h_in[n * D + i];
        int base = i * D + o;
#pragma unroll
        for (int j = 0; j < D; j++) acc[j] += hv * s_w2[j * 256 + base];
        bt += hv * s_b2[base];
    }
    float4* gd = (float4*)(g_gmat + (size_t)n * 256 + o * D);
    gd[0] = make_float4(acc[0], acc[1], acc[2], acc[3]);
    gd[1] = make_float4(acc[4], acc[5], acc[6], acc[7]);
    gd[2] = make_float4(acc[8], acc[9], acc[10], acc[11]);
    gd[3] = make_float4(acc[12], acc[13], acc[14], acc[15]);
    g_bt[gi] = bt;
}

// ---------------- K_msg: per src node, compute messages into dst slots ---------
// half-warp per node: lane o. g row held in registers.
__global__ void K_msg(int N) {
    int lane = threadIdx.x & 31;
    int wid  = threadIdx.x >> 5;
    int half = lane >> 4;
    int o    = lane & 15;
    int node = blockIdx.x * 16 + wid * 2 + half;

    int beg = 0, cnt = 0;
    if (node < N) { beg = g_off_src[node]; cnt = g_off_src[node + 1] - beg; }

    float ga[D];
    float btv = 0.f;
    if (node < N) {
#pragma unroll
        for (int j = 0; j < D; j++) ga[j] = g_gmat[(size_t)node * 256 + o * D + j];
        btv = g_bt[node * D + o];
    } else {
#pragma unroll
        for (int j = 0; j < D; j++) ga[j] = 0.f;
    }

    int other = __shfl_xor_sync(0xffffffffu, cnt, 16);
    int cmax = cnt > other ? cnt : other;
    int sbase = lane & 16;

    for (int t = 0; t < cmax; t++) {
        bool valid = (t < cnt);
        int ps = beg + t;
        float hev = 0.f;
        if (valid) hev = g_he_s[(size_t)ps * D + o];
        float m = btv;
#pragma unroll
        for (int j = 0; j < D; j++)
            m += __shfl_sync(0xffffffffu, hev, sbase + j) * ga[j];
        if (valid) {
            int pd = g_ds[ps];
            g_msg[(size_t)pd * D + o] = m;
        }
    }
}

// ---------------- K_agg: aggregate (fixed-point) + root term + BN stats --------
__global__ void K_agg(const float* __restrict__ h_in,
                      const float* __restrict__ root,
                      const float* __restrict__ conv_bias,
                      int layer, int N) {
    __shared__ float s_root[D * D];
    __shared__ float s_bias[D];
    __shared__ unsigned long long s_sum[D];
    __shared__ unsigned long long s_sq[D];
    int tid = threadIdx.x;
    if (tid < D * D) s_root[tid] = root[layer * D * D + tid];
    if (tid < D)     s_bias[tid] = conv_bias[layer * D + tid];
    if (tid < D)     { s_sum[tid] = 0ull; s_sq[tid] = 0ull; }
    __syncthreads();

    int lane = tid & 31;
    int wid  = tid >> 5;
    int half = lane >> 4;
    int o    = lane & 15;
    int node = blockIdx.x * 16 + wid * 2 + half;

    int beg = 0, cnt = 0;
    if (node < N) { beg = g_off_dst[node]; cnt = g_off_dst[node + 1] - beg; }

    long long acc = 0;
    for (int p = beg; p < beg + cnt; p++) {
        float v = g_msg[(size_t)p * D + o];
        acc += (long long)llrintf(v * FP_SCALE);
    }
    float aggv = (float)((double)acc * FP_INV);
    int degc = cnt > 0 ? cnt : 1;
    aggv /= (float)degc;

    float hv = (node < N) ? h_in[node * D + o] : 0.f;
    float hs = aggv + s_bias[o];
    int sbase = lane & 16;
#pragma unroll
    for (int i = 0; i < D; i++)
        hs += __shfl_sync(0xffffffffu, hv, sbase + i) * s_root[i * D + o];

    if (node < N) {
        g_hpre[node * D + o] = hs;
        atomicAdd(&s_sum[o], (unsigned long long)(long long)llrintf(hs * FP_SCALE));
        atomicAdd(&s_sq[o],  (unsigned long long)(long long)llrintf(hs * hs * FP_SCALE));
    }
    __syncthreads();
    if (tid < D) {
        atomicAdd((unsigned long long*)&g_bnsum[tid],      s_sum[tid]);
        atomicAdd((unsigned long long*)&g_bnsum[D + tid],  s_sq[tid]);
    }
}

// ---------------- K_bnact: batchnorm + tanh -----------------------------------
__global__ void K_bnact(const float* __restrict__ gamma,
                        const float* __restrict__ beta,
                        float* __restrict__ h_out,
                        int layer, int N) {
    int gi = blockIdx.x * blockDim.x + threadIdx.x;
    if (gi >= N * D) return;
    int o = gi & 15;
    double sum = (double)g_bnsum[o]     * FP_INV;
    double sq  = (double)g_bnsum[D + o] * FP_INV;
    double mu  = sum / (double)N;
    double var = sq / (double)N - mu * mu;
    float scale = gamma[layer * D + o] * rsqrtf((float)(var + 1e-5));
    float val = (g_hpre[gi] - (float)mu) * scale + beta[layer * D + o];
    h_out[gi] = tanhf(val);
}

// ---------------- K_pool: per-graph mean/max/min/sum ---------------------------
__global__ void K_pool(const float* __restrict__ hid,
                       const int*   __restrict__ lengths,
                       float* __restrict__ pooled,
                       int N) {
    int g = blockIdx.x;
    int t = threadIdx.x;          // 128 threads: c = t&15, r = t>>4 (8 rows)
    int c = t & 15, r = t >> 4;
    int nb = g_goff[g];
    int ne = g_goff[g + 1];
    if (ne > N) ne = N;

    float s = 0.f, mx = -3.402823e38f, mn = 3.402823e38f;
    for (int i = nb + r; i < ne; i += 8) {
        float v = hid[i * D + c];
        s += v;
        mx = fmaxf(mx, v);
        mn = fminf(mn, v);
    }
    __shared__ float shs[128], shx[128], shn[128];
    shs[t] = s; shx[t] = mx; shn[t] = mn;
    __syncthreads();
    for (int off = 64; off >= 16; off >>= 1) {
        if (t < off) {
            shs[t] += shs[t + off];
            shx[t] = fmaxf(shx[t], shx[t + off]);
            shn[t] = fminf(shn[t], shn[t + off]);
        }
        __syncthreads();
    }
    if (t < D) {
        float cntf = fmaxf((float)lengths[g], 1.f);
        float ssum = shs[t];
        pooled[g * 64 + t]          = ssum / cntf;
        pooled[g * 64 + 16 + t]     = shx[t];
        pooled[g * 64 + 32 + t]     = shn[t];
        pooled[g * 64 + 48 + t]     = ssum;
    }
}

// ---------------- K_fc: readout MLP + log_softmax ------------------------------
__global__ void K_fc(const float* __restrict__ pooled,
                     const float* __restrict__ fc1_w, const float* __restrict__ fc1_b,
                     const float* __restrict__ fc2_w, const float* __restrict__ fc2_b,
                     float* __restrict__ fc_out, float* __restrict__ ls_out,
                     int G) {
    int g = blockIdx.x * blockDim.x + threadIdx.x;
    if (g >= G) return;
    const float* p = pooled + (size_t)g * 64;
    float t16[16];
#pragma unroll
    for (int c = 0; c < 16; c++) {
        float a = fc1_b[c];
        for (int k = 0; k < 64; k++) a += p[k] * fc1_w[k * 16 + c];
        t16[c] = tanhf(a);
    }
    float fcv[10];
    float m = -3.402823e38f;
#pragma unroll
    for (int c = 0; c < 10; c++) {
        float a = fc2_b[c];
#pragma unroll
        for (int k = 0; k < 16; k++) a += t16[k] * fc2_w[k * 10 + c];
        fcv[c] = a;
        fc_out[g * 10 + c] = a;
        m = fmaxf(m, a);
    }
    float se = 0.f;
#pragma unroll
    for (int c = 0; c < 10; c++) se += expf(fcv[c] - m);
    float lse = logf(se) + m;
#pragma unroll
    for (int c = 0; c < 10; c++) ls_out[g * 10 + c] = fcv[c] - lse;
}

// =============================== host launcher =================================
extern "C" void kernel_launch(void* const* d_in, const int* in_sizes, int n_in,
                              void* d_out, int out_size) {
    const float* x         = (const float*)d_in[0];
    const float* edge_attr = (const float*)d_in[1];
    const float* edge_w1   = (const float*)d_in[2];
    const float* edge_b1   = (const float*)d_in[3];
    const float* edge_w2   = (const float*)d_in[4];
    const float* edge_b2   = (const float*)d_in[5];
    const float* root      = (const float*)d_in[6];
    const float* conv_bias = (const float*)d_in[7];
    const float* bn_gamma  = (const float*)d_in[8];
    const float* bn_beta   = (const float*)d_in[9];
    const float* fc1_w     = (const float*)d_in[10];
    const float* fc1_b     = (const float*)d_in[11];
    const float* fc2_w     = (const float*)d_in[12];
    const float* fc2_b     = (const float*)d_in[13];
    const int*   edge_index= (const int*)d_in[14];
    const int*   lengths   = (const int*)d_in[15];

    int N = in_sizes[0] / D;
    int E = in_sizes[1] / EF;
    int G = in_sizes[15];

    float* out        = (float*)d_out;
    float* out_hidden = out;
    float* out_pooled = out + (size_t)N * D;
    float* out_fc     = out_pooled + (size_t)G * 64;
    float* out_ls     = out_fc + (size_t)G * 10;

    // ---- setup: degrees, CSR, graph offsets (once per launch) ----
    K_zero<<<(N + 255) / 256, 256>>>(N);
    K_edge<<<(E + 127) / 128, 128>>>(edge_attr, edge_w1, edge_b1, edge_index, E);
    K_scan<<<1, 1024>>>(0, (const int*)0, N);
    K_scan<<<1, 1024>>>(1, (const int*)0, N);
    K_scan<<<1, 1024>>>(2, lengths, G);
    K_fill<<<(E + 255) / 256, 256>>>(edge_index, E);

    int nodeBlocks = (N + 15) / 16;
    int elemBlocks = (N * D + 255) / 256;

    // ---- layers ----
    for (int l = 0; l < NLAYERS; l++) {
        const float* h_in = (l == 0) ? x : g_hbuf;
        float* h_out = (l == NLAYERS - 1) ? out_hidden : g_hbuf;
        K_g<<<elemBlocks, 256>>>(h_in, edge_w2, edge_b2, N);
        K_msg<<<nodeBlocks, 256>>>(N);
        K_agg<<<nodeBlocks, 256>>>(h_in, root, conv_bias, l, N);
        K_bnact<<<elemBlocks, 256>>>(bn_gamma, bn_beta, h_out, l, N);
    }

    // ---- pooling + readout ----
    K_pool<<<G, 128>>>(out_hidden, lengths, out_pooled, N);
    K_fc<<<(G + 127) / 128, 128>>>(out_pooled, fc1_w, fc1_b, fc2_w, fc2_b,
                                   out_fc, out_ls, G);
}

// round 2
// speedup vs baseline: 1.2423x; 1.2423x over previous
#include <cuda_runtime.h>
#include <math.h>

#define D 16
#define EF 8
#define NLAYERS 3
#define MAX_N 50048
#define MAX_E 500224
#define SCB 128
#define FP_SCALE 4294967296.0f
#define FP_INV 2.3283064365386963e-10

// ---------------- static device scratch ----------------
__device__ float g_he_s[MAX_E * D];          // edge MLP output, src-CSR order
__device__ float g_msg [MAX_E * D];          // messages, dst-CSR order
__device__ int   g_ds  [MAX_E];              // src-slot -> dst-slot
__device__ int   g_deg [2][MAX_N];           // 0=src deg, 1=dst deg
__device__ int   g_off [2][MAX_N + 1];       // CSR offsets
__device__ int   g_cur [2][MAX_N];           // fill cursors
__device__ int   g_part[2][SCB];             // scan partials
__device__ float g_gmat[MAX_N * 256];        // per-node transform g[n][o*16+j]
__device__ float g_bt  [MAX_N * D];          // per-node bias term
__device__ float g_hbuf[MAX_N * D];          // inter-layer features
__device__ float g_hpre[MAX_N * D];          // pre-BN activations
__device__ unsigned long long g_bnsum[32];   // fixed-point BN sum / sumsq

// fast tanh: ~6 instr (FMUL + MUFU.EX2 + FADD x2 + MUFU.RCP path), err ~1e-7
__device__ __forceinline__ float ftanh(float x) {
    x = fminf(fmaxf(x, -15.f), 15.f);
    float e = __expf(2.f * x);
    return __fdividef(e - 1.f, e + 1.f);
}

// block exclusive scan of one int per thread; total left in s_w[32]
__device__ __forceinline__ int blk_ex_scan(int v, int* s_w) {
    int tid = threadIdx.x, lane = tid & 31, wid = tid >> 5;
    int nw = blockDim.x >> 5;
    int x = v;
#pragma unroll
    for (int d = 1; d < 32; d <<= 1) {
        int y = __shfl_up_sync(0xffffffffu, x, d);
        if (lane >= d) x += y;
    }
    if (lane == 31) s_w[wid] = x;
    __syncthreads();
    if (wid == 0) {
        int w = (lane < nw) ? s_w[lane] : 0;
        int xw = w;
#pragma unroll
        for (int d = 1; d < 32; d <<= 1) {
            int y = __shfl_up_sync(0xffffffffu, xw, d);
            if (lane >= d) xw += y;
        }
        if (lane < nw) s_w[lane] = xw - w;
        if (lane == 31) s_w[32] = xw;   // inclusive total
    }
    __syncthreads();
    return s_w[wid] + (x - v);
}

// ---------------- K_zero ----------------
__global__ void K_zero(int N) {
    int i = blockIdx.x * blockDim.x + threadIdx.x;
    if (i < N) {
        g_deg[0][i] = 0; g_deg[1][i] = 0;
        g_cur[0][i] = 0; g_cur[1][i] = 0;
    }
}

// ---------------- K_deg: degree counts ----------------
__global__ void K_deg(const int* __restrict__ ei, int E) {
    int e = blockIdx.x * blockDim.x + threadIdx.x;
    if (e >= E) return;
    atomicAdd(&g_deg[0][ei[e]], 1);
    atomicAdd(&g_deg[1][ei[E + e]], 1);
}

// ---------------- K_s1: per-block partial sums (grid SCB x 2) ----------------
__global__ void K_s1(int n) {
    int a = blockIdx.y;
    int chunk = (n + SCB - 1) / SCB;
    int beg = blockIdx.x * chunk;
    int end = min(n, beg + chunk);
    int s = 0;
    for (int i = beg + threadIdx.x; i < end; i += blockDim.x) s += g_deg[a][i];
    __shared__ int sw[8];
    int lane = threadIdx.x & 31, wid = threadIdx.x >> 5;
#pragma unroll
    for (int o = 16; o; o >>= 1) s += __shfl_down_sync(0xffffffffu, s, o);
    if (lane == 0) sw[wid] = s;
    __syncthreads();
    if (threadIdx.x == 0) {
        int t = 0;
        for (int w = 0; w < (int)(blockDim.x >> 5); w++) t += sw[w];
        g_part[a][blockIdx.x] = t;
    }
}

// ---------------- K_s2: scan the SCB partials (grid 1 x 2, block SCB) --------
__global__ void K_s2() {
    __shared__ int s_w[33];
    int a = blockIdx.y;
    int v = g_part[a][threadIdx.x];
    int ex = blk_ex_scan(v, s_w);
    g_part[a][threadIdx.x] = ex;
}

// ---------------- K_s3: apply — write CSR offsets (grid SCB x 2) -------------
__global__ void K_s3(int n) {
    __shared__ int s_w[33];
    int a = blockIdx.y;
    int chunk = (n + SCB - 1) / SCB;
    int beg = blockIdx.x * chunk;
    int end = min(n, beg + chunk);
    int base = g_part[a][blockIdx.x];
    for (int t0 = beg; t0 < end; t0 += blockDim.x) {
        int i = t0 + threadIdx.x;
        int v = (i < end) ? g_deg[a][i] : 0;
        int ex = blk_ex_scan(v, s_w);
        int tot = s_w[32];
        __syncthreads();
        if (i < end) g_off[a][i] = base + ex;
        base += tot;
    }
    if (blockIdx.x == SCB - 1 && threadIdx.x == 0) g_off[a][n] = base;
}

// ---------------- K_edgefill: edge MLP -> CSR slot + dst-slot map ------------
__global__ void K_edgefill(const float* __restrict__ edge_attr,
                           const float* __restrict__ w1,
                           const float* __restrict__ b1,
                           const int*   __restrict__ ei, int E) {
    __shared__ float s_w1[EF * D];
    __shared__ float s_b1[D];
    int tid = threadIdx.x;
    if (tid < EF * D) s_w1[tid] = w1[tid];
    if (tid < D)      s_b1[tid] = b1[tid];
    __syncthreads();

    int e = blockIdx.x * blockDim.x + tid;
    if (e >= E) return;

    const float4* ea = (const float4*)(edge_attr + (size_t)e * EF);
    float4 a0 = ea[0], a1 = ea[1];
    float a[8] = {a0.x, a0.y, a0.z, a0.w, a1.x, a1.y, a1.z, a1.w};

    float out[D];
#pragma unroll
    for (int j = 0; j < D; j++) {
        float acc = s_b1[j];
#pragma unroll
        for (int k = 0; k < EF; k++) acc += a[k] * s_w1[k * D + j];
        out[j] = ftanh(acc);
    }

    int s = ei[e];
    int d = ei[E + e];
    int ps = g_off[0][s] + atomicAdd(&g_cur[0][s], 1);
    int pd = g_off[1][d] + atomicAdd(&g_cur[1][d], 1);
    g_ds[ps] = pd;
    float4* dst4 = (float4*)(g_he_s + (size_t)ps * D);
    dst4[0] = make_float4(out[0], out[1], out[2], out[3]);
    dst4[1] = make_float4(out[4], out[5], out[6], out[7]);
    dst4[2] = make_float4(out[8], out[9], out[10], out[11]);
    dst4[3] = make_float4(out[12], out[13], out[14], out[15]);
}

// ---------------- K_g: per-node transform, 2 nodes/thread --------------------
// g[n][o][j] = sum_i h[n][i] * w2[j*256 + i*16 + o]
__global__ void __launch_bounds__(256) K_g(const float* __restrict__ h_in,
                                           const float* __restrict__ w2,
                                           const float* __restrict__ b2,
                                           int N) {
    __shared__ float s_w2[D * 256];
    __shared__ float s_b2[256];
    int tid = threadIdx.x;
    for (int i = tid; i < D * 256; i += blockDim.x) s_w2[i] = w2[i];
    for (int i = tid; i < 256; i += blockDim.x)     s_b2[i] = b2[i];
    if (blockIdx.x == 0 && tid < 32) g_bnsum[tid] = 0ull;  // reset BN accum
    __syncthreads();

    int gi = blockIdx.x * blockDim.x + tid;
    int o = gi & 15, nq = gi >> 4;
    int n0 = nq * 2;
    if (n0 >= N) return;
    bool ok1 = (n0 + 1 < N);

    float hv0[D], hv1[D];
    {
        const float4* h4 = (const float4*)(h_in + (size_t)n0 * D);
        float4 v;
        v = h4[0]; hv0[0]=v.x; hv0[1]=v.y; hv0[2]=v.z; hv0[3]=v.w;
        v = h4[1]; hv0[4]=v.x; hv0[5]=v.y; hv0[6]=v.z; hv0[7]=v.w;
        v = h4[2]; hv0[8]=v.x; hv0[9]=v.y; hv0[10]=v.z; hv0[11]=v.w;
        v = h4[3]; hv0[12]=v.x; hv0[13]=v.y; hv0[14]=v.z; hv0[15]=v.w;
        if (ok1) {
            v = h4[4]; hv1[0]=v.x; hv1[1]=v.y; hv1[2]=v.z; hv1[3]=v.w;
            v = h4[5]; hv1[4]=v.x; hv1[5]=v.y; hv1[6]=v.z; hv1[7]=v.w;
            v = h4[6]; hv1[8]=v.x; hv1[9]=v.y; hv1[10]=v.z; hv1[11]=v.w;
            v = h4[7]; hv1[12]=v.x; hv1[13]=v.y; hv1[14]=v.z; hv1[15]=v.w;
        } else {
#pragma unroll
            for (int i = 0; i < D; i++) hv1[i] = 0.f;
        }
    }

    float acc0[D], acc1[D];
#pragma unroll
    for (int j = 0; j < D; j++) { acc0[j] = 0.f; acc1[j] = 0.f; }
    float bt0 = 0.f, bt1 = 0.f;
#pragma unroll
    for (int i = 0; i < D; i++) {
        int base = i * D + o;
#pragma unroll
        for (int j = 0; j < D; j++) {
            float w = s_w2[j * 256 + base];
            acc0[j] += hv0[i] * w;
            acc1[j] += hv1[i] * w;
        }
        float b = s_b2[base];
        bt0 += hv0[i] * b;
        bt1 += hv1[i] * b;
    }

    float4* gd0 = (float4*)(g_gmat + (size_t)n0 * 256 + o * D);
    gd0[0] = make_float4(acc0[0], acc0[1], acc0[2], acc0[3]);
    gd0[1] = make_float4(acc0[4], acc0[5], acc0[6], acc0[7]);
    gd0[2] = make_float4(acc0[8], acc0[9], acc0[10], acc0[11]);
    gd0[3] = make_float4(acc0[12], acc0[13], acc0[14], acc0[15]);
    g_bt[n0 * D + o] = bt0;
    if (ok1) {
        float4* gd1 = (float4*)(g_gmat + (size_t)(n0 + 1) * 256 + o * D);
        gd1[0] = make_float4(acc1[0], acc1[1], acc1[2], acc1[3]);
        gd1[1] = make_float4(acc1[4], acc1[5], acc1[6], acc1[7]);
        gd1[2] = make_float4(acc1[8], acc1[9], acc1[10], acc1[11]);
        gd1[3] = make_float4(acc1[12], acc1[13], acc1[14], acc1[15]);
        g_bt[(n0 + 1) * D + o] = bt1;
    }
}

// ---------------- K_msg: per src node messages (half-warp/node, no shfl) -----
__global__ void K_msg(int N) {
    int lane = threadIdx.x & 31;
    int wid  = threadIdx.x >> 5;
    int half = lane >> 4;
    int o    = lane & 15;
    int node = blockIdx.x * 16 + wid * 2 + half;
    if (node >= N) return;

    int beg = g_off[0][node];
    int end = g_off[0][node + 1];
    if (beg == end) return;

    float ga[D];
    {
        const float4* g4 = (const float4*)(g_gmat + (size_t)node * 256 + o * D);
        float4 v;
        v = g4[0]; ga[0]=v.x; ga[1]=v.y; ga[2]=v.z; ga[3]=v.w;
        v = g4[1]; ga[4]=v.x; ga[5]=v.y; ga[6]=v.z; ga[7]=v.w;
        v = g4[2]; ga[8]=v.x; ga[9]=v.y; ga[10]=v.z; ga[11]=v.w;
        v = g4[3]; ga[12]=v.x; ga[13]=v.y; ga[14]=v.z; ga[15]=v.w;
    }
    float btv = g_bt[node * D + o];

#pragma unroll 2
    for (int ps = beg; ps < end; ps++) {
        const float4* he4 = (const float4*)(g_he_s + (size_t)ps * D);
        float4 h0 = he4[0], h1 = he4[1], h2 = he4[2], h3 = he4[3];
        float m = btv;
        m += h0.x*ga[0]  + h0.y*ga[1]  + h0.z*ga[2]  + h0.w*ga[3];
        m += h1.x*ga[4]  + h1.y*ga[5]  + h1.z*ga[6]  + h1.w*ga[7];
        m += h2.x*ga[8]  + h2.y*ga[9]  + h2.z*ga[10] + h2.w*ga[11];
        m += h3.x*ga[12] + h3.y*ga[13] + h3.z*ga[14] + h3.w*ga[15];
        g_msg[(size_t)g_ds[ps] * D + o] = m;
    }
}

// ---------------- K_agg: fixed-point aggregate + root + BN stats -------------
__global__ void K_agg(const float* __restrict__ h_in,
                      const float* __restrict__ root,
                      const float* __restrict__ conv_bias,
                      int layer, int N) {
    __shared__ float s_root[D * D];
    __shared__ float s_bias[D];
    __shared__ unsigned long long s_sum[D];
    __shared__ unsigned long long s_sq[D];
    int tid = threadIdx.x;
    if (tid < D * D) s_root[tid] = root[layer * D * D + tid];
    if (tid < D)     s_bias[tid] = conv_bias[layer * D + tid];
    if (tid < D)     { s_sum[tid] = 0ull; s_sq[tid] = 0ull; }
    __syncthreads();

    int lane = tid & 31;
    int wid  = tid >> 5;
    int half = lane >> 4;
    int o    = lane & 15;
    int node = blockIdx.x * 16 + wid * 2 + half;

    if (node < N) {
        int beg = g_off[1][node];
        int cnt = g_off[1][node + 1] - beg;

        long long acc = 0;
#pragma unroll 2
        for (int p = beg; p < beg + cnt; p++) {
            float v = g_msg[(size_t)p * D + o];
            acc += (long long)llrintf(v * FP_SCALE);
        }
        float aggv = (float)((double)acc * FP_INV);
        aggv /= (float)(cnt > 0 ? cnt : 1);

        float hv[D];
        const float4* h4 = (const float4*)(h_in + (size_t)node * D);
        float4 v4;
        v4 = h4[0]; hv[0]=v4.x; hv[1]=v4.y; hv[2]=v4.z; hv[3]=v4.w;
        v4 = h4[1]; hv[4]=v4.x; hv[5]=v4.y; hv[6]=v4.z; hv[7]=v4.w;
        v4 = h4[2]; hv[8]=v4.x; hv[9]=v4.y; hv[10]=v4.z; hv[11]=v4.w;
        v4 = h4[3]; hv[12]=v4.x; hv[13]=v4.y; hv[14]=v4.z; hv[15]=v4.w;

        float hs = aggv + s_bias[o];
#pragma unroll
        for (int i = 0; i < D; i++) hs += hv[i] * s_root[i * D + o];

        g_hpre[node * D + o] = hs;
        atomicAdd(&s_sum[o], (unsigned long long)(long long)llrintf(hs * FP_SCALE));
        atomicAdd(&s_sq[o],  (unsigned long long)(long long)llrintf(hs * hs * FP_SCALE));
    }
    __syncthreads();
    if (tid < D) {
        atomicAdd(&g_bnsum[tid],     s_sum[tid]);
        atomicAdd(&g_bnsum[D + tid], s_sq[tid]);
    }
}

// ---------------- K_bnact: batchnorm + tanh ----------------------------------
__global__ void K_bnact(const float* __restrict__ gamma,
                        const float* __restrict__ beta,
                        float* __restrict__ h_out,
                        int layer, int N) {
    int gi = blockIdx.x * blockDim.x + threadIdx.x;
    if (gi >= N * D) return;
    int o = gi & 15;
    double sum = (double)(long long)g_bnsum[o]     * FP_INV;
    double sq  = (double)(long long)g_bnsum[D + o] * FP_INV;
    double mu  = sum / (double)N;
    double var = sq / (double)N - mu * mu;
    float scale = gamma[layer * D + o] * rsqrtf((float)(var + 1e-5));
    float val = (g_hpre[gi] - (float)mu) * scale + beta[layer * D + o];
    h_out[gi] = ftanh(val);
}

// ---------------- K_poolfc: pooling + readout MLP + log_softmax --------------
__global__ void K_poolfc(const float* __restrict__ hid,
                         const int*   __restrict__ lengths,
                         const float* __restrict__ fc1_w, const float* __restrict__ fc1_b,
                         const float* __restrict__ fc2_w, const float* __restrict__ fc2_b,
                         float* __restrict__ pooled, float* __restrict__ fc_out,
                         float* __restrict__ ls_out, int N, int G) {
    int g = blockIdx.x, t = threadIdx.x;   // 128 threads
    __shared__ float shs[128], shx[128], shn[128];
    __shared__ int swi[4];
    __shared__ int s_nb;
    __shared__ float sp[64], st16[16], sfc[16];
    __shared__ float s_lse;

    // prefix of lengths -> node base for this graph
    int acc = 0;
    for (int i = t; i < g; i += 128) acc += lengths[i];
#pragma unroll
    for (int off = 16; off; off >>= 1) acc += __shfl_down_sync(0xffffffffu, acc, off);
    if ((t & 31) == 0) swi[t >> 5] = acc;
    __syncthreads();
    if (t == 0) s_nb = swi[0] + swi[1] + swi[2] + swi[3];
    __syncthreads();
    int nb = s_nb;
    int len = lengths[g];
    int ne = min(N, nb + len);

    int c = t & 15, r = t >> 4;
    float s = 0.f, mx = -3.402823e38f, mn = 3.402823e38f;
    for (int i = nb + r; i < ne; i += 8) {
        float v = hid[i * D + c];
        s += v; mx = fmaxf(mx, v); mn = fminf(mn, v);
    }
    shs[t] = s; shx[t] = mx; shn[t] = mn;
    __syncthreads();
    for (int off = 64; off >= 16; off >>= 1) {
        if (t < off) {
            shs[t] += shs[t + off];
            shx[t] = fmaxf(shx[t], shx[t + off]);
            shn[t] = fminf(shn[t], shn[t + off]);
        }
        __syncthreads();
    }
    if (t < D) {
        float cnt = fmaxf((float)len, 1.f);
        float ssum = shs[t];
        sp[t]      = ssum / cnt;
        sp[16 + t] = shx[t];
        sp[32 + t] = shn[t];
        sp[48 + t] = ssum;
        pooled[g * 64 + t]      = sp[t];
        pooled[g * 64 + 16 + t] = shx[t];
        pooled[g * 64 + 32 + t] = shn[t];
        pooled[g * 64 + 48 + t] = ssum;
    }
    __syncthreads();
    if (t < 16) {
        float a = fc1_b[t];
#pragma unroll
        for (int k = 0; k < 64; k++) a += sp[k] * fc1_w[k * 16 + t];
        st16[t] = ftanh(a);
    }
    __syncthreads();
    if (t < 10) {
        float a = fc2_b[t];
#pragma unroll
        for (int k = 0; k < 16; k++) a += st16[k] * fc2_w[k * 10 + t];
        sfc[t] = a;
        fc_out[g * 10 + t] = a;
    }
    __syncthreads();
    if (t == 0) {
        float m = sfc[0];
        for (int k = 1; k < 10; k++) m = fmaxf(m, sfc[k]);
        float se = 0.f;
        for (int k = 0; k < 10; k++) se += __expf(sfc[k] - m);
        s_lse = __logf(se) + m;
    }
    __syncthreads();
    if (t < 10) ls_out[g * 10 + t] = sfc[t] - s_lse;
}

// =============================== host launcher =================================
extern "C" void kernel_launch(void* const* d_in, const int* in_sizes, int n_in,
                              void* d_out, int out_size) {
    const float* x         = (const float*)d_in[0];
    const float* edge_attr = (const float*)d_in[1];
    const float* edge_w1   = (const float*)d_in[2];
    const float* edge_b1   = (const float*)d_in[3];
    const float* edge_w2   = (const float*)d_in[4];
    const float* edge_b2   = (const float*)d_in[5];
    const float* root      = (const float*)d_in[6];
    const float* conv_bias = (const float*)d_in[7];
    const float* bn_gamma  = (const float*)d_in[8];
    const float* bn_beta   = (const float*)d_in[9];
    const float* fc1_w     = (const float*)d_in[10];
    const float* fc1_b     = (const float*)d_in[11];
    const float* fc2_w     = (const float*)d_in[12];
    const float* fc2_b     = (const float*)d_in[13];
    const int*   edge_index= (const int*)d_in[14];
    const int*   lengths   = (const int*)d_in[15];

    int N = in_sizes[0] / D;
    int E = in_sizes[1] / EF;
    int G = in_sizes[15];

    float* out        = (float*)d_out;
    float* out_hidden = out;
    float* out_pooled = out + (size_t)N * D;
    float* out_fc     = out_pooled + (size_t)G * 64;
    float* out_ls     = out_fc + (size_t)G * 10;

    // ---- setup: degrees + multi-block scans + fused edge-MLP/CSR fill ----
    K_zero<<<(N + 255) / 256, 256>>>(N);
    K_deg <<<(E + 255) / 256, 256>>>(edge_index, E);
    K_s1  <<<dim3(SCB, 2), 256>>>(N);
    K_s2  <<<dim3(1, 2), SCB>>>();
    K_s3  <<<dim3(SCB, 2), 256>>>(N);
    K_edgefill<<<(E + 127) / 128, 128>>>(edge_attr, edge_w1, edge_b1, edge_index, E);

    int nodeBlocks = (N + 15) / 16;
    int elemBlocks = (N * D + 255) / 256;
    int gBlocks    = (((N + 1) / 2) * 16 + 255) / 256;

    // ---- layers ----
    for (int l = 0; l < NLAYERS; l++) {
        const float* h_in = (l == 0) ? x : g_hbuf;
        float* h_out = (l == NLAYERS - 1) ? out_hidden : g_hbuf;
        K_g    <<<gBlocks, 256>>>(h_in, edge_w2, edge_b2, N);
        K_msg  <<<nodeBlocks, 256>>>(N);
        K_agg  <<<nodeBlocks, 256>>>(h_in, root, conv_bias, l, N);
        K_bnact<<<elemBlocks, 256>>>(bn_gamma, bn_beta, h_out, l, N);
    }

    // ---- pooling + readout (fused) ----
    K_poolfc<<<G, 128>>>(out_hidden, lengths, fc1_w, fc1_b, fc2_w, fc2_b,
                         out_pooled, out_fc, out_ls, N, G);
}

// round 4
// speedup vs baseline: 1.5449x; 1.2436x over previous
#include <cuda_runtime.h>
#include <math.h>

#define D 16
#define EF 8
#define NLAYERS 3
#define MAX_N 50048
#define MAX_E 500224
#define SCB 128
#define FP_SCALE 4294967296.0f
#define FP_INV 2.3283064365386963e-10

// ---------------- static device scratch ----------------
struct ZeroBlk {                             // zeroed by one cudaMemsetAsync
    int deg[2][MAX_N];                       // 0=src deg, 1=dst deg
    int cur[2][MAX_N];                       // fill cursors
};
__device__ ZeroBlk g_z;

__device__ float g_he_s[MAX_E * D];          // edge MLP output, src-CSR order
__device__ float g_msg [MAX_E * D];          // messages, dst-CSR order
__device__ int   g_ds  [MAX_E];              // src-slot -> dst-slot
__device__ int   g_off [2][MAX_N + 1];       // CSR offsets
__device__ int   g_part[2][SCB];             // scan partials
__device__ float g_gmat[MAX_N * 256];        // per-node transform g[n][o*16+j]
__device__ float g_bt  [MAX_N * D];          // per-node bias term
__device__ float g_hbuf[MAX_N * D];          // activated features (layer input)
__device__ float g_hpre[MAX_N * D];          // pre-BN activations
__device__ unsigned long long g_bnsum[32];   // fixed-point BN sum / sumsq

// fast tanh (EX2 + fast divide), err ~1e-7
__device__ __forceinline__ float ftanh(float x) {
    x = fminf(fmaxf(x, -15.f), 15.f);
    float e = __expf(2.f * x);
    return __fdividef(e - 1.f, e + 1.f);
}

// block exclusive scan of one int per thread; total left in s_w[32]
__device__ __forceinline__ int blk_ex_scan(int v, int* s_w) {
    int tid = threadIdx.x, lane = tid & 31, wid = tid >> 5;
    int nw = blockDim.x >> 5;
    int x = v;
#pragma unroll
    for (int d = 1; d < 32; d <<= 1) {
        int y = __shfl_up_sync(0xffffffffu, x, d);
        if (lane >= d) x += y;
    }
    if (lane == 31) s_w[wid] = x;
    __syncthreads();
    if (wid == 0) {
        int w = (lane < nw) ? s_w[lane] : 0;
        int xw = w;
#pragma unroll
        for (int d = 1; d < 32; d <<= 1) {
            int y = __shfl_up_sync(0xffffffffu, xw, d);
            if (lane >= d) xw += y;
        }
        if (lane < nw) s_w[lane] = xw - w;
        if (lane == 31) s_w[32] = xw;
    }
    __syncthreads();
    return s_w[wid] + (x - v);
}

// ---------------- K_deg ----------------
__global__ void K_deg(const int* __restrict__ ei, int E) {
    int e = blockIdx.x * blockDim.x + threadIdx.x;
    if (e >= E) return;
    atomicAdd(&g_z.deg[0][ei[e]], 1);
    atomicAdd(&g_z.deg[1][ei[E + e]], 1);
}

// ---------------- K_s1: per-block partial sums (grid SCB x 2) ----------------
__global__ void K_s1(int n) {
    int a = blockIdx.y;
    int chunk = (n + SCB - 1) / SCB;
    int beg = blockIdx.x * chunk;
    int end = min(n, beg + chunk);
    int s = 0;
    for (int i = beg + threadIdx.x; i < end; i += blockDim.x) s += g_z.deg[a][i];
    __shared__ int sw[8];
    int lane = threadIdx.x & 31, wid = threadIdx.x >> 5;
#pragma unroll
    for (int o = 16; o; o >>= 1) s += __shfl_down_sync(0xffffffffu, s, o);
    if (lane == 0) sw[wid] = s;
    __syncthreads();
    if (threadIdx.x == 0) {
        int t = 0;
        for (int w = 0; w < (int)(blockDim.x >> 5); w++) t += sw[w];
        g_part[a][blockIdx.x] = t;
    }
}

// ---------------- K_s2: scan the SCB partials ----------------
__global__ void K_s2() {
    __shared__ int s_w[33];
    int a = blockIdx.y;
    int v = g_part[a][threadIdx.x];
    int ex = blk_ex_scan(v, s_w);
    g_part[a][threadIdx.x] = ex;
}

// ---------------- K_s3: apply — write CSR offsets ----------------
__global__ void K_s3(int n) {
    __shared__ int s_w[33];
    int a = blockIdx.y;
    int chunk = (n + SCB - 1) / SCB;
    int beg = blockIdx.x * chunk;
    int end = min(n, beg + chunk);
    int base = g_part[a][blockIdx.x];
    for (int t0 = beg; t0 < end; t0 += blockDim.x) {
        int i = t0 + threadIdx.x;
        int v = (i < end) ? g_z.deg[a][i] : 0;
        int ex = blk_ex_scan(v, s_w);
        int tot = s_w[32];
        __syncthreads();
        if (i < end) g_off[a][i] = base + ex;
        base += tot;
    }
    if (blockIdx.x == SCB - 1 && threadIdx.x == 0) g_off[a][n] = base;
}

// ---------------- K_edgefill: edge MLP -> CSR slot + dst-slot map ------------
__global__ void K_edgefill(const float* __restrict__ edge_attr,
                           const float* __restrict__ w1,
                           const float* __restrict__ b1,
                           const int*   __restrict__ ei, int E) {
    __shared__ float s_w1[EF * D];
    __shared__ float s_b1[D];
    int tid = threadIdx.x;
    if (tid < EF * D) s_w1[tid] = w1[tid];
    if (tid < D)      s_b1[tid] = b1[tid];
    __syncthreads();

    int e = blockIdx.x * blockDim.x + tid;
    if (e >= E) return;

    const float4* ea = (const float4*)(edge_attr + (size_t)e * EF);
    float4 a0 = ea[0], a1 = ea[1];
    float a[8] = {a0.x, a0.y, a0.z, a0.w, a1.x, a1.y, a1.z, a1.w};

    float out[D];
#pragma unroll
    for (int j = 0; j < D; j++) {
        float acc = s_b1[j];
#pragma unroll
        for (int k = 0; k < EF; k++) acc += a[k] * s_w1[k * D + j];
        out[j] = ftanh(acc);
    }

    int s = ei[e];
    int d = ei[E + e];
    int ps = g_off[0][s] + atomicAdd(&g_z.cur[0][s], 1);
    int pd = g_off[1][d] + atomicAdd(&g_z.cur[1][d], 1);
    g_ds[ps] = pd;
    float4* dst4 = (float4*)(g_he_s + (size_t)ps * D);
    dst4[0] = make_float4(out[0], out[1], out[2], out[3]);
    dst4[1] = make_float4(out[4], out[5], out[6], out[7]);
    dst4[2] = make_float4(out[8], out[9], out[10], out[11]);
    dst4[3] = make_float4(out[12], out[13], out[14], out[15]);
}

// ---------------- K_g: per-node transform, 2 nodes/thread (R2-proven) --------
__global__ void __launch_bounds__(256) K_g(const float* __restrict__ h_in,
                                           const float* __restrict__ w2,
                                           const float* __restrict__ b2,
                                           int N) {
    __shared__ float s_w2[D * 256];
    __shared__ float s_b2[256];
    int tid = threadIdx.x;
    for (int i = tid; i < D * 256; i += blockDim.x) s_w2[i] = w2[i];
    for (int i = tid; i < 256; i += blockDim.x)     s_b2[i] = b2[i];
    if (blockIdx.x == 0 && tid < 32) g_bnsum[tid] = 0ull;  // reset BN accum (R2)
    __syncthreads();

    int gi = blockIdx.x * blockDim.x + tid;
    int o = gi & 15, nq = gi >> 4;
    int n0 = nq * 2;
    if (n0 >= N) return;
    bool ok1 = (n0 + 1 < N);

    float hv0[D], hv1[D];
    {
        const float4* h4 = (const float4*)(h_in + (size_t)n0 * D);
        float4 v;
        v = h4[0]; hv0[0]=v.x; hv0[1]=v.y; hv0[2]=v.z; hv0[3]=v.w;
        v = h4[1]; hv0[4]=v.x; hv0[5]=v.y; hv0[6]=v.z; hv0[7]=v.w;
        v = h4[2]; hv0[8]=v.x; hv0[9]=v.y; hv0[10]=v.z; hv0[11]=v.w;
        v = h4[3]; hv0[12]=v.x; hv0[13]=v.y; hv0[14]=v.z; hv0[15]=v.w;
        if (ok1) {
            v = h4[4]; hv1[0]=v.x; hv1[1]=v.y; hv1[2]=v.z; hv1[3]=v.w;
            v = h4[5]; hv1[4]=v.x; hv1[5]=v.y; hv1[6]=v.z; hv1[7]=v.w;
            v = h4[6]; hv1[8]=v.x; hv1[9]=v.y; hv1[10]=v.z; hv1[11]=v.w;
            v = h4[7]; hv1[12]=v.x; hv1[13]=v.y; hv1[14]=v.z; hv1[15]=v.w;
        } else {
#pragma unroll
            for (int i = 0; i < D; i++) hv1[i] = 0.f;
        }
    }

    float acc0[D], acc1[D];
#pragma unroll
    for (int j = 0; j < D; j++) { acc0[j] = 0.f; acc1[j] = 0.f; }
    float bt0 = 0.f, bt1 = 0.f;
#pragma unroll
    for (int i = 0; i < D; i++) {
        int base = i * D + o;
#pragma unroll
        for (int j = 0; j < D; j++) {
            float w = s_w2[j * 256 + base];
            acc0[j] += hv0[i] * w;
            acc1[j] += hv1[i] * w;
        }
        float b = s_b2[base];
        bt0 += hv0[i] * b;
        bt1 += hv1[i] * b;
    }

    float4* gd0 = (float4*)(g_gmat + (size_t)n0 * 256 + o * D);
    gd0[0] = make_float4(acc0[0], acc0[1], acc0[2], acc0[3]);
    gd0[1] = make_float4(acc0[4], acc0[5], acc0[6], acc0[7]);
    gd0[2] = make_float4(acc0[8], acc0[9], acc0[10], acc0[11]);
    gd0[3] = make_float4(acc0[12], acc0[13], acc0[14], acc0[15]);
    g_bt[n0 * D + o] = bt0;
    if (ok1) {
        float4* gd1 = (float4*)(g_gmat + (size_t)(n0 + 1) * 256 + o * D);
        gd1[0] = make_float4(acc1[0], acc1[1], acc1[2], acc1[3]);
        gd1[1] = make_float4(acc1[4], acc1[5], acc1[6], acc1[7]);
        gd1[2] = make_float4(acc1[8], acc1[9], acc1[10], acc1[11]);
        gd1[3] = make_float4(acc1[12], acc1[13], acc1[14], acc1[15]);
        g_bt[(n0 + 1) * D + o] = bt1;
    }
}

// ---------------- K_msg: per src node messages, 4 edges batched --------------
__global__ void K_msg(int N) {
    int lane = threadIdx.x & 31;
    int wid  = threadIdx.x >> 5;
    int half = lane >> 4;
    int o    = lane & 15;
    int node = blockIdx.x * 16 + wid * 2 + half;
    if (node >= N) return;

    int beg = g_off[0][node];
    int end = g_off[0][node + 1];
    if (beg == end) return;

    float ga[D];
    {
        const float4* g4 = (const float4*)(g_gmat + (size_t)node * 256 + o * D);
        float4 v;
        v = g4[0]; ga[0]=v.x; ga[1]=v.y; ga[2]=v.z; ga[3]=v.w;
        v = g4[1]; ga[4]=v.x; ga[5]=v.y; ga[6]=v.z; ga[7]=v.w;
        v = g4[2]; ga[8]=v.x; ga[9]=v.y; ga[10]=v.z; ga[11]=v.w;
        v = g4[3]; ga[12]=v.x; ga[13]=v.y; ga[14]=v.z; ga[15]=v.w;
    }
    float btv = g_bt[node * D + o];

    int ps = beg;
    // 4-edge batches: 16 independent LDG.128 + 4 ds loads up front (MLP~20)
    for (; ps + 4 <= end; ps += 4) {
        const float4* b4 = (const float4*)(g_he_s + (size_t)ps * D);
        float4 r0 = b4[0],  r1 = b4[1],  r2 = b4[2],  r3 = b4[3];
        float4 r4 = b4[4],  r5 = b4[5],  r6 = b4[6],  r7 = b4[7];
        float4 r8 = b4[8],  r9 = b4[9],  rA = b4[10], rB = b4[11];
        float4 rC = b4[12], rD = b4[13], rE = b4[14], rF = b4[15];
        int d0 = g_ds[ps], d1 = g_ds[ps+1], d2 = g_ds[ps+2], d3 = g_ds[ps+3];

        float m0 = btv, m1 = btv, m2 = btv, m3 = btv;
        m0 += r0.x*ga[0]+r0.y*ga[1]+r0.z*ga[2]+r0.w*ga[3]
            + r1.x*ga[4]+r1.y*ga[5]+r1.z*ga[6]+r1.w*ga[7]
            + r2.x*ga[8]+r2.y*ga[9]+r2.z*ga[10]+r2.w*ga[11]
            + r3.x*ga[12]+r3.y*ga[13]+r3.z*ga[14]+r3.w*ga[15];
        m1 += r4.x*ga[0]+r4.y*ga[1]+r4.z*ga[2]+r4.w*ga[3]
            + r5.x*ga[4]+r5.y*ga[5]+r5.z*ga[6]+r5.w*ga[7]
            + r6.x*ga[8]+r6.y*ga[9]+r6.z*ga[10]+r6.w*ga[11]
            + r7.x*ga[12]+r7.y*ga[13]+r7.z*ga[14]+r7.w*ga[15];
        m2 += r8.x*ga[0]+r8.y*ga[1]+r8.z*ga[2]+r8.w*ga[3]
            + r9.x*ga[4]+r9.y*ga[5]+r9.z*ga[6]+r9.w*ga[7]
            + rA.x*ga[8]+rA.y*ga[9]+rA.z*ga[10]+rA.w*ga[11]
            + rB.x*ga[12]+rB.y*ga[13]+rB.z*ga[14]+rB.w*ga[15];
        m3 += rC.x*ga[0]+rC.y*ga[1]+rC.z*ga[2]+rC.w*ga[3]
            + rD.x*ga[4]+rD.y*ga[5]+rD.z*ga[6]+rD.w*ga[7]
            + rE.x*ga[8]+rE.y*ga[9]+rE.z*ga[10]+rE.w*ga[11]
            + rF.x*ga[12]+rF.y*ga[13]+rF.z*ga[14]+rF.w*ga[15];

        g_msg[(size_t)d0 * D + o] = m0;
        g_msg[(size_t)d1 * D + o] = m1;
        g_msg[(size_t)d2 * D + o] = m2;
        g_msg[(size_t)d3 * D + o] = m3;
    }
    for (; ps < end; ps++) {
        const float4* he4 = (const float4*)(g_he_s + (size_t)ps * D);
        float4 h0 = he4[0], h1 = he4[1], h2 = he4[2], h3 = he4[3];
        float m = btv;
        m += h0.x*ga[0]  + h0.y*ga[1]  + h0.z*ga[2]  + h0.w*ga[3];
        m += h1.x*ga[4]  + h1.y*ga[5]  + h1.z*ga[6]  + h1.w*ga[7];
        m += h2.x*ga[8]  + h2.y*ga[9]  + h2.z*ga[10] + h2.w*ga[11];
        m += h3.x*ga[12] + h3.y*ga[13] + h3.z*ga[14] + h3.w*ga[15];
        g_msg[(size_t)g_ds[ps] * D + o] = m;
    }
}

// ---------------- K_agg: aggregate + root term + BN stats --------------------
__global__ void K_agg(const float* __restrict__ h_in,
                      const float* __restrict__ root,
                      const float* __restrict__ conv_bias,
                      int layer, int N) {
    __shared__ float s_root[D * D];
    __shared__ float s_bias[D];
    __shared__ unsigned long long s_sum[D];
    __shared__ unsigned long long s_sq[D];
    int tid = threadIdx.x;
    if (tid < D * D) s_root[tid] = root[layer * D * D + tid];
    if (tid < D)     s_bias[tid] = conv_bias[layer * D + tid];
    if (tid < D)     { s_sum[tid] = 0ull; s_sq[tid] = 0ull; }
    __syncthreads();

    int lane = tid & 31;
    int wid  = tid >> 5;
    int half = lane >> 4;
    int o    = lane & 15;
    int node = blockIdx.x * 16 + wid * 2 + half;

    if (node < N) {
        int beg = g_off[1][node];
        int end = g_off[1][node + 1];
        int cnt = end - beg;

        long long acc = 0;
        int p = beg;
        for (; p + 4 <= end; p += 4) {
            float v0 = g_msg[(size_t)p * D + o];
            float v1 = g_msg[(size_t)(p+1) * D + o];
            float v2 = g_msg[(size_t)(p+2) * D + o];
            float v3 = g_msg[(size_t)(p+3) * D + o];
            acc += (long long)llrintf(v0 * FP_SCALE);
            acc += (long long)llrintf(v1 * FP_SCALE);
            acc += (long long)llrintf(v2 * FP_SCALE);
            acc += (long long)llrintf(v3 * FP_SCALE);
        }
        for (; p < end; p++) {
            float v = g_msg[(size_t)p * D + o];
            acc += (long long)llrintf(v * FP_SCALE);
        }
        float aggv = (float)((double)acc * FP_INV);
        aggv = __fdividef(aggv, (float)(cnt > 0 ? cnt : 1));

        float hv[D];
        const float4* h4 = (const float4*)(h_in + (size_t)node * D);
        float4 v4;
        v4 = h4[0]; hv[0]=v4.x; hv[1]=v4.y; hv[2]=v4.z; hv[3]=v4.w;
        v4 = h4[1]; hv[4]=v4.x; hv[5]=v4.y; hv[6]=v4.z; hv[7]=v4.w;
        v4 = h4[2]; hv[8]=v4.x; hv[9]=v4.y; hv[10]=v4.z; hv[11]=v4.w;
        v4 = h4[3]; hv[12]=v4.x; hv[13]=v4.y; hv[14]=v4.z; hv[15]=v4.w;

        float hs = aggv + s_bias[o];
#pragma unroll
        for (int i = 0; i < D; i++) hs += hv[i] * s_root[i * D + o];

        g_hpre[node * D + o] = hs;
        atomicAdd(&s_sum[o], (unsigned long long)(long long)llrintf(hs * FP_SCALE));
        atomicAdd(&s_sq[o],  (unsigned long long)(long long)llrintf(hs * hs * FP_SCALE));
    }
    __syncthreads();
    if (tid < D) {
        atomicAdd(&g_bnsum[tid],     s_sum[tid]);
        atomicAdd(&g_bnsum[D + tid], s_sq[tid]);
    }
}

// ---------------- K_bnact: batchnorm + tanh (coeffs hoisted to preamble) -----
__global__ void K_bnact(const float* __restrict__ gamma,
                        const float* __restrict__ beta,
                        float* __restrict__ h_out,
                        int layer, int N) {
    __shared__ float s_sc[D], s_sh[D];
    int tid = threadIdx.x;
    if (tid < D) {
        double sum = (double)(long long)g_bnsum[tid]     * FP_INV;
        double sq  = (double)(long long)g_bnsum[D + tid] * FP_INV;
        double inv = 1.0 / (double)N;
        double mu  = sum * inv;
        double var = sq * inv - mu * mu;
        float sc = gamma[layer * D + tid] * rsqrtf((float)(var + 1e-5));
        s_sc[tid] = sc;
        s_sh[tid] = beta[layer * D + tid] - (float)mu * sc;
    }
    __syncthreads();
    int gi = blockIdx.x * blockDim.x + tid;
    if (gi >= N * D) return;
    int o = gi & 15;
    h_out[gi] = ftanh(g_hpre[gi] * s_sc[o] + s_sh[o]);
}

// ---------------- K_poolfc: pooling + readout MLP + log_softmax --------------
__global__ void K_poolfc(const float* __restrict__ hid,
                         const int*   __restrict__ lengths,
                         const float* __restrict__ fc1_w, const float* __restrict__ fc1_b,
                         const float* __restrict__ fc2_w, const float* __restrict__ fc2_b,
                         float* __restrict__ pooled, float* __restrict__ fc_out,
                         float* __restrict__ ls_out, int N, int G) {
    int g = blockIdx.x, t = threadIdx.x;   // 128 threads
    __shared__ float shs[128], shx[128], shn[128];
    __shared__ int swi[4];
    __shared__ int s_nb;
    __shared__ float sp[64], st16[16], sfc[16];
    __shared__ float s_lse;

    // prefix of lengths -> node base for this graph
    int acc = 0;
    for (int i = t; i < g; i += 128) acc += lengths[i];
#pragma unroll
    for (int off = 16; off; off >>= 1) acc += __shfl_down_sync(0xffffffffu, acc, off);
    if ((t & 31) == 0) swi[t >> 5] = acc;
    __syncthreads();
    if (t == 0) s_nb = swi[0] + swi[1] + swi[2] + swi[3];
    __syncthreads();
    int nb = s_nb;
    int len = lengths[g];
    int ne = min(N, nb + len);

    int c = t & 15, r = t >> 4;
    float s = 0.f, mx = -3.402823e38f, mn = 3.402823e38f;
    for (int i = nb + r; i < ne; i += 8) {
        float v = hid[i * D + c];
        s += v; mx = fmaxf(mx, v); mn = fminf(mn, v);
    }
    shs[t] = s; shx[t] = mx; shn[t] = mn;
    __syncthreads();
    for (int off = 64; off >= 16; off >>= 1) {
        if (t < off) {
            shs[t] += shs[t + off];
            shx[t] = fmaxf(shx[t], shx[t + off]);
            shn[t] = fminf(shn[t], shn[t + off]);
        }
        __syncthreads();
    }
    if (t < D) {
        float cnt = fmaxf((float)len, 1.f);
        float ssum = shs[t];
        sp[t]      = __fdividef(ssum, cnt);
        sp[16 + t] = shx[t];
        sp[32 + t] = shn[t];
        sp[48 + t] = ssum;
        pooled[g * 64 + t]      = sp[t];
        pooled[g * 64 + 16 + t] = shx[t];
        pooled[g * 64 + 32 + t] = shn[t];
        pooled[g * 64 + 48 + t] = ssum;
    }
    __syncthreads();
    if (t < 16) {
        float a = fc1_b[t];
#pragma unroll
        for (int k = 0; k < 64; k++) a += sp[k] * fc1_w[k * 16 + t];
        st16[t] = ftanh(a);
    }
    __syncthreads();
    if (t < 10) {
        float a = fc2_b[t];
#pragma unroll
        for (int k = 0; k < 16; k++) a += st16[k] * fc2_w[k * 10 + t];
        sfc[t] = a;
        fc_out[g * 10 + t] = a;
    }
    __syncthreads();
    if (t == 0) {
        float m = sfc[0];
        for (int k = 1; k < 10; k++) m = fmaxf(m, sfc[k]);
        float se = 0.f;
        for (int k = 0; k < 10; k++) se += __expf(sfc[k] - m);
        s_lse = __logf(se) + m;
    }
    __syncthreads();
    if (t < 10) ls_out[g * 10 + t] = sfc[t] - s_lse;
}

// =============================== host launcher =================================
extern "C" void kernel_launch(void* const* d_in, const int* in_sizes, int n_in,
                              void* d_out, int out_size) {
    const float* x         = (const float*)d_in[0];
    const float* edge_attr = (const float*)d_in[1];
    const float* edge_w1   = (const float*)d_in[2];
    const float* edge_b1   = (const float*)d_in[3];
    const float* edge_w2   = (const float*)d_in[4];
    const float* edge_b2   = (const float*)d_in[5];
    const float* root      = (const float*)d_in[6];
    const float* conv_bias = (const float*)d_in[7];
    const float* bn_gamma  = (const float*)d_in[8];
    const float* bn_beta   = (const float*)d_in[9];
    const float* fc1_w     = (const float*)d_in[10];
    const float* fc1_b     = (const float*)d_in[11];
    const float* fc2_w     = (const float*)d_in[12];
    const float* fc2_b     = (const float*)d_in[13];
    const int*   edge_index= (const int*)d_in[14];
    const int*   lengths   = (const int*)d_in[15];

    int N = in_sizes[0] / D;
    int E = in_sizes[1] / EF;
    int G = in_sizes[15];

    float* out        = (float*)d_out;
    float* out_hidden = out;
    float* out_pooled = out + (size_t)N * D;
    float* out_fc     = out_pooled + (size_t)G * 64;
    float* out_ls     = out_fc + (size_t)G * 10;

    // ---- setup: one memset for all counters, then degrees + scans + fill ----
    void* zp = 0;
    cudaGetSymbolAddress(&zp, g_z);
    cudaMemsetAsync(zp, 0, sizeof(ZeroBlk));

    K_deg <<<(E + 255) / 256, 256>>>(edge_index, E);
    K_s1  <<<dim3(SCB, 2), 256>>>(N);
    K_s2  <<<dim3(1, 2), SCB>>>();
    K_s3  <<<dim3(SCB, 2), 256>>>(N);
    K_edgefill<<<(E + 127) / 128, 128>>>(edge_attr, edge_w1, edge_b1, edge_index, E);

    int nodeBlocks = (N + 15) / 16;
    int elemBlocks = (N * D + 255) / 256;
    int gBlocks    = (((N + 1) / 2) * 16 + 255) / 256;

    // ---- layers (R2-proven structure) ----
    for (int l = 0; l < NLAYERS; l++) {
        const float* h_in = (l == 0) ? x : g_hbuf;
        float* h_out = (l == NLAYERS - 1) ? out_hidden : g_hbuf;
        K_g    <<<gBlocks, 256>>>(h_in, edge_w2, edge_b2, N);
        K_msg  <<<nodeBlocks, 256>>>(N);
        K_agg  <<<nodeBlocks, 256>>>(h_in, root, conv_bias, l, N);
        K_bnact<<<elemBlocks, 256>>>(bn_gamma, bn_beta, h_out, l, N);
    }

    // ---- pooling + readout ----
    K_poolfc<<<G, 128>>>(out_hidden, lengths, fc1_w, fc1_b, fc2_w, fc2_b,
                         out_pooled, out_fc, out_ls, N, G);
}

// round 5
// speedup vs baseline: 1.9947x; 1.2912x over previous
#include <cuda_runtime.h>
#include <math.h>

#define D 16
#define EF 8
#define NLAYERS 3
#define MAX_N 50048
#define MAX_E 500224
#define SCB 128
#define FP_SCALE 4294967296.0f
#define FP_INV 2.3283064365386963e-10

// ---------------- static device scratch ----------------
struct ZeroBlk {                             // zeroed by ONE cudaMemsetAsync
    unsigned long long acc[MAX_N * D];       // fixed-point message accumulators
    int deg[2][MAX_N];                       // 0=src deg, 1=dst deg (dst: mean only)
    int cur[MAX_N];                          // src-CSR fill cursor
};
__device__ ZeroBlk g_z;

__device__ float g_he_s[MAX_E * D];          // edge MLP output, src-CSR order
__device__ int   g_dn  [MAX_E];              // src-slot -> dst NODE id
__device__ int   g_off [MAX_N + 1];          // src-CSR offsets
__device__ int   g_part[SCB];                // scan partials
__device__ float g_hbuf[MAX_N * D];          // activated features (layer input)
__device__ float g_hpre[MAX_N * D];          // pre-BN activations
__device__ unsigned long long g_bnsum[32];   // fixed-point BN sum / sumsq

// fast tanh (EX2 + fast divide), err ~1e-7
__device__ __forceinline__ float ftanh(float x) {
    x = fminf(fmaxf(x, -15.f), 15.f);
    float e = __expf(2.f * x);
    return __fdividef(e - 1.f, e + 1.f);
}

// block exclusive scan of one int per thread; total left in s_w[32]
__device__ __forceinline__ int blk_ex_scan(int v, int* s_w) {
    int tid = threadIdx.x, lane = tid & 31, wid = tid >> 5;
    int nw = blockDim.x >> 5;
    int x = v;
#pragma unroll
    for (int d = 1; d < 32; d <<= 1) {
        int y = __shfl_up_sync(0xffffffffu, x, d);
        if (lane >= d) x += y;
    }
    if (lane == 31) s_w[wid] = x;
    __syncthreads();
    if (wid == 0) {
        int w = (lane < nw) ? s_w[lane] : 0;
        int xw = w;
#pragma unroll
        for (int d = 1; d < 32; d <<= 1) {
            int y = __shfl_up_sync(0xffffffffu, xw, d);
            if (lane >= d) xw += y;
        }
        if (lane < nw) s_w[lane] = xw - w;
        if (lane == 31) s_w[32] = xw;
    }
    __syncthreads();
    return s_w[wid] + (x - v);
}

// ---------------- K_deg ----------------
__global__ void K_deg(const int* __restrict__ ei, int E) {
    int e = blockIdx.x * blockDim.x + threadIdx.x;
    if (e >= E) return;
    atomicAdd(&g_z.deg[0][ei[e]], 1);
    atomicAdd(&g_z.deg[1][ei[E + e]], 1);
}

// ---------------- K_s1: per-block partial sums over src degrees --------------
__global__ void K_s1(int n) {
    int chunk = (n + SCB - 1) / SCB;
    int beg = blockIdx.x * chunk;
    int end = min(n, beg + chunk);
    int s = 0;
    for (int i = beg + threadIdx.x; i < end; i += blockDim.x) s += g_z.deg[0][i];
    __shared__ int sw[8];
    int lane = threadIdx.x & 31, wid = threadIdx.x >> 5;
#pragma unroll
    for (int o = 16; o; o >>= 1) s += __shfl_down_sync(0xffffffffu, s, o);
    if (lane == 0) sw[wid] = s;
    __syncthreads();
    if (threadIdx.x == 0) {
        int t = 0;
        for (int w = 0; w < (int)(blockDim.x >> 5); w++) t += sw[w];
        g_part[blockIdx.x] = t;
    }
}

// ---------------- K_s2: scan the SCB partials ----------------
__global__ void K_s2() {
    __shared__ int s_w[33];
    int v = g_part[threadIdx.x];
    int ex = blk_ex_scan(v, s_w);
    g_part[threadIdx.x] = ex;
}

// ---------------- K_s3: apply — write src-CSR offsets ----------------
__global__ void K_s3(int n) {
    __shared__ int s_w[33];
    int chunk = (n + SCB - 1) / SCB;
    int beg = blockIdx.x * chunk;
    int end = min(n, beg + chunk);
    int base = g_part[blockIdx.x];
    for (int t0 = beg; t0 < end; t0 += blockDim.x) {
        int i = t0 + threadIdx.x;
        int v = (i < end) ? g_z.deg[0][i] : 0;
        int ex = blk_ex_scan(v, s_w);
        int tot = s_w[32];
        __syncthreads();
        if (i < end) g_off[i] = base + ex;
        base += tot;
    }
    if (blockIdx.x == SCB - 1 && threadIdx.x == 0) g_off[n] = base;
}

// ---------------- K_edgefill: edge MLP -> src-CSR slot + dst node id ---------
__global__ void K_edgefill(const float* __restrict__ edge_attr,
                           const float* __restrict__ w1,
                           const float* __restrict__ b1,
                           const int*   __restrict__ ei, int E) {
    __shared__ float s_w1[EF * D];
    __shared__ float s_b1[D];
    int tid = threadIdx.x;
    if (tid < EF * D) s_w1[tid] = w1[tid];
    if (tid < D)      s_b1[tid] = b1[tid];
    __syncthreads();

    int e = blockIdx.x * blockDim.x + tid;
    if (e >= E) return;

    const float4* ea = (const float4*)(edge_attr + (size_t)e * EF);
    float4 a0 = ea[0], a1 = ea[1];
    float a[8] = {a0.x, a0.y, a0.z, a0.w, a1.x, a1.y, a1.z, a1.w};

    float out[D];
#pragma unroll
    for (int j = 0; j < D; j++) {
        float acc = s_b1[j];
#pragma unroll
        for (int k = 0; k < EF; k++) acc += a[k] * s_w1[k * D + j];
        out[j] = ftanh(acc);
    }

    int s = ei[e];
    int d = ei[E + e];
    int ps = g_off[s] + atomicAdd(&g_z.cur[s], 1);
    g_dn[ps] = d;
    float4* dst4 = (float4*)(g_he_s + (size_t)ps * D);
    dst4[0] = make_float4(out[0], out[1], out[2], out[3]);
    dst4[1] = make_float4(out[4], out[5], out[6], out[7]);
    dst4[2] = make_float4(out[8], out[9], out[10], out[11]);
    dst4[3] = make_float4(out[12], out[13], out[14], out[15]);
}

// ---------------- K_gmsg: fused per-node transform + message scatter ---------
// Half-warp per node, lane o. acc[j] = g[n][o][j] computed in registers, then
// messages for all out-edges are RED.ADD.U64'd into g_acc[dst] (deterministic).
__global__ void __launch_bounds__(256) K_gmsg(const float* __restrict__ h_in,
                                              const float* __restrict__ w2,
                                              const float* __restrict__ b2,
                                              int N) {
    __shared__ float s_w2[D * 256];
    __shared__ float s_b2[256];
    int tid = threadIdx.x;
    for (int i = tid; i < D * 256; i += blockDim.x) s_w2[i] = w2[i];
    for (int i = tid; i < 256; i += blockDim.x)     s_b2[i] = b2[i];
    if (blockIdx.x == 0 && tid < 32) g_bnsum[tid] = 0ull;  // reset BN accum
    __syncthreads();

    int o    = tid & 15;
    int node = blockIdx.x * 16 + (tid >> 4);
    if (node >= N) return;

    // load this node's feature row (broadcast across the 16 lanes)
    float hv[D];
    {
        const float4* h4 = (const float4*)(h_in + (size_t)node * D);
        float4 v;
        v = h4[0]; hv[0]=v.x; hv[1]=v.y; hv[2]=v.z; hv[3]=v.w;
        v = h4[1]; hv[4]=v.x; hv[5]=v.y; hv[6]=v.z; hv[7]=v.w;
        v = h4[2]; hv[8]=v.x; hv[9]=v.y; hv[10]=v.z; hv[11]=v.w;
        v = h4[3]; hv[12]=v.x; hv[13]=v.y; hv[14]=v.z; hv[15]=v.w;
    }

    // per-node transform: ga[j] = sum_i h[i] * w2[j*256 + i*16 + o], bt likewise
    float ga[D];
#pragma unroll
    for (int j = 0; j < D; j++) ga[j] = 0.f;
    float btv = 0.f;
#pragma unroll
    for (int i = 0; i < D; i++) {
        float h = hv[i];
        int base = i * D + o;
#pragma unroll
        for (int j = 0; j < D; j++) ga[j] += h * s_w2[j * 256 + base];
        btv += h * s_b2[base];
    }

    // message loop over out-edges (src-CSR contiguous), 4-edge batches
    int beg = g_off[node];
    int end = g_off[node + 1];
    int ps = beg;
    for (; ps + 4 <= end; ps += 4) {
        const float4* b4 = (const float4*)(g_he_s + (size_t)ps * D);
        float4 r0 = b4[0],  r1 = b4[1],  r2 = b4[2],  r3 = b4[3];
        float4 r4 = b4[4],  r5 = b4[5],  r6 = b4[6],  r7 = b4[7];
        float4 r8 = b4[8],  r9 = b4[9],  rA = b4[10], rB = b4[11];
        float4 rC = b4[12], rD = b4[13], rE = b4[14], rF = b4[15];
        int d0 = g_dn[ps], d1 = g_dn[ps+1], d2 = g_dn[ps+2], d3 = g_dn[ps+3];

        float m0 = btv, m1 = btv, m2 = btv, m3 = btv;
        m0 += r0.x*ga[0]+r0.y*ga[1]+r0.z*ga[2]+r0.w*ga[3]
            + r1.x*ga[4]+r1.y*ga[5]+r1.z*ga[6]+r1.w*ga[7]
            + r2.x*ga[8]+r2.y*ga[9]+r2.z*ga[10]+r2.w*ga[11]
            + r3.x*ga[12]+r3.y*ga[13]+r3.z*ga[14]+r3.w*ga[15];
        m1 += r4.x*ga[0]+r4.y*ga[1]+r4.z*ga[2]+r4.w*ga[3]
            + r5.x*ga[4]+r5.y*ga[5]+r5.z*ga[6]+r5.w*ga[7]
            + r6.x*ga[8]+r6.y*ga[9]+r6.z*ga[10]+r6.w*ga[11]
            + r7.x*ga[12]+r7.y*ga[13]+r7.z*ga[14]+r7.w*ga[15];
        m2 += r8.x*ga[0]+r8.y*ga[1]+r8.z*ga[2]+r8.w*ga[3]
            + r9.x*ga[4]+r9.y*ga[5]+r9.z*ga[6]+r9.w*ga[7]
            + rA.x*ga[8]+rA.y*ga[9]+rA.z*ga[10]+rA.w*ga[11]
            + rB.x*ga[12]+rB.y*ga[13]+rB.z*ga[14]+rB.w*ga[15];
        m3 += rC.x*ga[0]+rC.y*ga[1]+rC.z*ga[2]+rC.w*ga[3]
            + rD.x*ga[4]+rD.y*ga[5]+rD.z*ga[6]+rD.w*ga[7]
            + rE.x*ga[8]+rE.y*ga[9]+rE.z*ga[10]+rE.w*ga[11]
            + rF.x*ga[12]+rF.y*ga[13]+rF.z*ga[14]+rF.w*ga[15];

        atomicAdd(&g_z.acc[(size_t)d0 * D + o], (unsigned long long)(long long)llrintf(m0 * FP_SCALE));
        atomicAdd(&g_z.acc[(size_t)d1 * D + o], (unsigned long long)(long long)llrintf(m1 * FP_SCALE));
        atomicAdd(&g_z.acc[(size_t)d2 * D + o], (unsigned long long)(long long)llrintf(m2 * FP_SCALE));
        atomicAdd(&g_z.acc[(size_t)d3 * D + o], (unsigned long long)(long long)llrintf(m3 * FP_SCALE));
    }
    for (; ps < end; ps++) {
        const float4* he4 = (const float4*)(g_he_s + (size_t)ps * D);
        float4 h0 = he4[0], h1 = he4[1], h2 = he4[2], h3 = he4[3];
        float m = btv;
        m += h0.x*ga[0]  + h0.y*ga[1]  + h0.z*ga[2]  + h0.w*ga[3];
        m += h1.x*ga[4]  + h1.y*ga[5]  + h1.z*ga[6]  + h1.w*ga[7];
        m += h2.x*ga[8]  + h2.y*ga[9]  + h2.z*ga[10] + h2.w*ga[11];
        m += h3.x*ga[12] + h3.y*ga[13] + h3.z*ga[14] + h3.w*ga[15];
        atomicAdd(&g_z.acc[(size_t)g_dn[ps] * D + o], (unsigned long long)(long long)llrintf(m * FP_SCALE));
    }
}

// ---------------- K_agg: elementwise aggregate + root term + BN stats --------
__global__ void K_agg(const float* __restrict__ h_in,
                      const float* __restrict__ root,
                      const float* __restrict__ conv_bias,
                      int layer, int N) {
    __shared__ float s_root[D * D];
    __shared__ float s_bias[D];
    __shared__ unsigned long long s_sum[D];
    __shared__ unsigned long long s_sq[D];
    int tid = threadIdx.x;
    if (tid < D * D) s_root[tid] = root[layer * D * D + tid];
    if (tid < D)     s_bias[tid] = conv_bias[layer * D + tid];
    if (tid < D)     { s_sum[tid] = 0ull; s_sq[tid] = 0ull; }
    __syncthreads();

    int gi = blockIdx.x * blockDim.x + tid;
    int o = gi & 15, n = gi >> 4;

    if (n < N) {
        long long acc = (long long)g_z.acc[gi];
        g_z.acc[gi] = 0ull;                      // re-arm for next layer
        int deg = g_z.deg[1][n];
        if (deg == 0) deg = 1;
        float aggv = (float)((double)acc * FP_INV);
        aggv = __fdividef(aggv, (float)deg);

        float hv[D];
        const float4* h4 = (const float4*)(h_in + (size_t)n * D);
        float4 v4;
        v4 = h4[0]; hv[0]=v4.x; hv[1]=v4.y; hv[2]=v4.z; hv[3]=v4.w;
        v4 = h4[1]; hv[4]=v4.x; hv[5]=v4.y; hv[6]=v4.z; hv[7]=v4.w;
        v4 = h4[2]; hv[8]=v4.x; hv[9]=v4.y; hv[10]=v4.z; hv[11]=v4.w;
        v4 = h4[3]; hv[12]=v4.x; hv[13]=v4.y; hv[14]=v4.z; hv[15]=v4.w;

        float hs = aggv + s_bias[o];
#pragma unroll
        for (int i = 0; i < D; i++) hs += hv[i] * s_root[i * D + o];

        g_hpre[gi] = hs;
        atomicAdd(&s_sum[o], (unsigned long long)(long long)llrintf(hs * FP_SCALE));
        atomicAdd(&s_sq[o],  (unsigned long long)(long long)llrintf(hs * hs * FP_SCALE));
    }
    __syncthreads();
    if (tid < D) {
        atomicAdd(&g_bnsum[tid],     s_sum[tid]);
        atomicAdd(&g_bnsum[D + tid], s_sq[tid]);
    }
}

// ---------------- K_bnact: batchnorm + tanh (coeffs hoisted to preamble) -----
__global__ void K_bnact(const float* __restrict__ gamma,
                        const float* __restrict__ beta,
                        float* __restrict__ h_out,
                        int layer, int N) {
    __shared__ float s_sc[D], s_sh[D];
    int tid = threadIdx.x;
    if (tid < D) {
        double sum = (double)(long long)g_bnsum[tid]     * FP_INV;
        double sq  = (double)(long long)g_bnsum[D + tid] * FP_INV;
        double inv = 1.0 / (double)N;
        double mu  = sum * inv;
        double var = sq * inv - mu * mu;
        float sc = gamma[layer * D + tid] * rsqrtf((float)(var + 1e-5));
        s_sc[tid] = sc;
        s_sh[tid] = beta[layer * D + tid] - (float)mu * sc;
    }
    __syncthreads();
    int gi = blockIdx.x * blockDim.x + tid;
    if (gi >= N * D) return;
    int o = gi & 15;
    h_out[gi] = ftanh(g_hpre[gi] * s_sc[o] + s_sh[o]);
}

// ---------------- K_poolfc: pooling + readout MLP + log_softmax --------------
__global__ void K_poolfc(const float* __restrict__ hid,
                         const int*   __restrict__ lengths,
                         const float* __restrict__ fc1_w, const float* __restrict__ fc1_b,
                         const float* __restrict__ fc2_w, const float* __restrict__ fc2_b,
                         float* __restrict__ pooled, float* __restrict__ fc_out,
                         float* __restrict__ ls_out, int N, int G) {
    int g = blockIdx.x, t = threadIdx.x;   // 128 threads
    __shared__ float shs[128], shx[128], shn[128];
    __shared__ int swi[4];
    __shared__ int s_nb;
    __shared__ float sp[64], st16[16], sfc[16];
    __shared__ float s_lse;

    int acc = 0;
    for (int i = t; i < g; i += 128) acc += lengths[i];
#pragma unroll
    for (int off = 16; off; off >>= 1) acc += __shfl_down_sync(0xffffffffu, acc, off);
    if ((t & 31) == 0) swi[t >> 5] = acc;
    __syncthreads();
    if (t == 0) s_nb = swi[0] + swi[1] + swi[2] + swi[3];
    __syncthreads();
    int nb = s_nb;
    int len = lengths[g];
    int ne = min(N, nb + len);

    int c = t & 15, r = t >> 4;
    float s = 0.f, mx = -3.402823e38f, mn = 3.402823e38f;
    for (int i = nb + r; i < ne; i += 8) {
        float v = hid[i * D + c];
        s += v; mx = fmaxf(mx, v); mn = fminf(mn, v);
    }
    shs[t] = s; shx[t] = mx; shn[t] = mn;
    __syncthreads();
    for (int off = 64; off >= 16; off >>= 1) {
        if (t < off) {
            shs[t] += shs[t + off];
            shx[t] = fmaxf(shx[t], shx[t + off]);
            shn[t] = fminf(shn[t], shn[t + off]);
        }
        __syncthreads();
    }
    if (t < D) {
        float cnt = fmaxf((float)len, 1.f);
        float ssum = shs[t];
        sp[t]      = __fdividef(ssum, cnt);
        sp[16 + t] = shx[t];
        sp[32 + t] = shn[t];
        sp[48 + t] = ssum;
        pooled[g * 64 + t]      = sp[t];
        pooled[g * 64 + 16 + t] = shx[t];
        pooled[g * 64 + 32 + t] = shn[t];
        pooled[g * 64 + 48 + t] = ssum;
    }
    __syncthreads();
    if (t < 16) {
        float a = fc1_b[t];
#pragma unroll
        for (int k = 0; k < 64; k++) a += sp[k] * fc1_w[k * 16 + t];
        st16[t] = ftanh(a);
    }
    __syncthreads();
    if (t < 10) {
        float a = fc2_b[t];
#pragma unroll
        for (int k = 0; k < 16; k++) a += st16[k] * fc2_w[k * 10 + t];
        sfc[t] = a;
        fc_out[g * 10 + t] = a;
    }
    __syncthreads();
    if (t == 0) {
        float m = sfc[0];
        for (int k = 1; k < 10; k++) m = fmaxf(m, sfc[k]);
        float se = 0.f;
        for (int k = 0; k < 10; k++) se += __expf(sfc[k] - m);
        s_lse = __logf(se) + m;
    }
    __syncthreads();
    if (t < 10) ls_out[g * 10 + t] = sfc[t] - s_lse;
}

// =============================== host launcher =================================
extern "C" void kernel_launch(void* const* d_in, const int* in_sizes, int n_in,
                              void* d_out, int out_size) {
    const float* x         = (const float*)d_in[0];
    const float* edge_attr = (const float*)d_in[1];
    const float* edge_w1   = (const float*)d_in[2];
    const float* edge_b1   = (const float*)d_in[3];
    const float* edge_w2   = (const float*)d_in[4];
    const float* edge_b2   = (const float*)d_in[5];
    const float* root      = (const float*)d_in[6];
    const float* conv_bias = (const float*)d_in[7];
    const float* bn_gamma  = (const float*)d_in[8];
    const float* bn_beta   = (const float*)d_in[9];
    const float* fc1_w     = (const float*)d_in[10];
    const float* fc1_b     = (const float*)d_in[11];
    const float* fc2_w     = (const float*)d_in[12];
    const float* fc2_b     = (const float*)d_in[13];
    const int*   edge_index= (const int*)d_in[14];
    const int*   lengths   = (const int*)d_in[15];

    int N = in_sizes[0] / D;
    int E = in_sizes[1] / EF;
    int G = in_sizes[15];

    float* out        = (float*)d_out;
    float* out_hidden = out;
    float* out_pooled = out + (size_t)N * D;
    float* out_fc     = out_pooled + (size_t)G * 64;
    float* out_ls     = out_fc + (size_t)G * 10;

    // ---- setup: one memset (acc + degrees + cursor), then CSR build ----
    void* zp = 0;
    cudaGetSymbolAddress(&zp, g_z);
    cudaMemsetAsync(zp, 0, sizeof(ZeroBlk));

    K_deg <<<(E + 255) / 256, 256>>>(edge_index, E);
    K_s1  <<<SCB, 256>>>(N);
    K_s2  <<<1, SCB>>>();
    K_s3  <<<SCB, 256>>>(N);
    K_edgefill<<<(E + 127) / 128, 128>>>(edge_attr, edge_w1, edge_b1, edge_index, E);

    int nodeBlocks = (N + 15) / 16;
    int elemBlocks = (N * D + 255) / 256;

    // ---- layers ----
    for (int l = 0; l < NLAYERS; l++) {
        const float* h_in = (l == 0) ? x : g_hbuf;
        float* h_out = (l == NLAYERS - 1) ? out_hidden : g_hbuf;
        K_gmsg <<<nodeBlocks, 256>>>(h_in, edge_w2, edge_b2, N);
        K_agg  <<<elemBlocks, 256>>>(h_in, root, conv_bias, l, N);
        K_bnact<<<elemBlocks, 256>>>(bn_gamma, bn_beta, h_out, l, N);
    }

    // ---- pooling + readout ----
    K_poolfc<<<G, 128>>>(out_hidden, lengths, fc1_w, fc1_b, fc2_w, fc2_b,
                         out_pooled, out_fc, out_ls, N, G);
}